// round 17
// baseline (speedup 1.0000x reference)
#include <cuda_runtime.h>
#include <stdint.h>
#include <math.h>

#define VSZ 32000
#define ESZ 400
#define HSZ 1150
#define HPAD 1152
#define BSZ 16
#define TSZ 128
#define GP12 4608
#define GP3  1600
#define FLAGSTRIDE 32
#define NSL 16

// ---------------- scratch ----------------
// split bf16 operand buffers (u32 word = 2 consecutive k, low half = even k)
__device__ uint32_t g_y0h[2048*200], g_y0l[2048*200];
__device__ uint32_t g_y1h[2048*576], g_y1l[2048*576];
__device__ uint32_t g_y2h[2048*576], g_y2l[2048*576];
__device__ uint32_t g_y3h[2048*200], g_y3l[2048*200];
__device__ uint32_t g_W1h[4600*200], g_W1l[4600*200];
__device__ uint32_t g_W2h[4600*576], g_W2l[4600*576];
__device__ uint32_t g_W3h[1600*576], g_W3l[1600*576];
__device__ uint32_t g_Eh[VSZ*200],   g_El[VSZ*200];
__device__ float g_pre[TSZ*BSZ*4*HSZ];
__device__ float g_Wt1[HSZ*GP12];
__device__ float g_Wt2[HSZ*GP12];
__device__ float g_Wt3[ESZ*GP3];
__device__ float g_hTa[HSZ*BSZ];
__device__ float g_hTb[HSZ*BSZ];
__device__ float g_cT1[HSZ*BSZ];
__device__ float g_cT2[HSZ*BSZ];
__device__ float g_cT3[ESZ*BSZ];
__device__ float g_hO1[HSZ*BSZ];
__device__ float g_hO2[HSZ*BSZ];
__device__ float g_hO3[ESZ*BSZ];
__device__ unsigned g_flags[3 * 144 * FLAGSTRIDE];

// ---------------- bf16 split helper ----------------
__device__ __forceinline__ void bfsplit2(float v0, float v1, uint32_t& h, uint32_t& l) {
    asm("cvt.rn.bf16x2.f32 %0, %1, %2;" : "=r"(h) : "f"(v1), "f"(v0));  // lo=v0, hi=v1
    float r0 = v0 - __uint_as_float(h << 16);
    float r1 = v1 - __uint_as_float(h & 0xffff0000u);
    asm("cvt.rn.bf16x2.f32 %0, %1, %2;" : "=r"(l) : "f"(r1), "f"(r0));
}

// ---------------- prep kernels (write split operands) ----------------
__global__ void split2_k(const float* __restrict__ src, uint32_t* __restrict__ dh,
                         uint32_t* __restrict__ dl, int nwords) {
    int i = blockIdx.x * blockDim.x + threadIdx.x;
    if (i >= nwords) return;
    float2 v = ((const float2*)src)[i];
    uint32_t h, l;
    bfsplit2(v.x, v.y, h, l);
    dh[i] = h; dl[i] = l;
}

__global__ void padsplit2_k(const float* __restrict__ src, uint32_t* __restrict__ dh,
                            uint32_t* __restrict__ dl, int rows, int Kin, int Kw) {
    int idx = blockIdx.x * blockDim.x + threadIdx.x;
    if (idx >= rows * Kw) return;
    int r = idx / Kw, j = idx % Kw;
    int k0 = 2 * j;
    float v0 = (k0 < Kin)     ? src[(size_t)r * Kin + k0]     : 0.f;
    float v1 = (k0 + 1 < Kin) ? src[(size_t)r * Kin + k0 + 1] : 0.f;
    uint32_t h, l;
    bfsplit2(v0, v1, h, l);
    dh[idx] = h; dl[idx] = l;
}

__global__ void embed2_k(const float* __restrict__ emb, const int* __restrict__ x,
                         uint32_t* __restrict__ dh, uint32_t* __restrict__ dl) {
    int idx = blockIdx.x * blockDim.x + threadIdx.x;
    const int Kw = ESZ / 2;
    if (idx >= TSZ * BSZ * Kw) return;
    int row = idx / Kw, j = idx % Kw;
    float2 v = ((const float2*)(emb + (size_t)x[row] * ESZ))[j];
    uint32_t h, l;
    bfsplit2(v.x, v.y, h, l);
    dh[idx] = h; dl[idx] = l;
}

__global__ void wtrans_k(const float* __restrict__ W, float* __restrict__ Wt,
                         int Hp, int Gp) {
    __shared__ float tile[32][33];
    int jblk = blockIdx.x;
    int k0   = blockIdx.y * 32;
    for (int rr = 0; rr < 32; rr += 8) {
        int r = rr + threadIdx.y;
        int g = r >> 3, u = r & 7;
        int j = jblk * 8 + u;
        int orow = g * Hp + j;
        int k = k0 + threadIdx.x;
        tile[r][threadIdx.x] = (j < Hp && k < Hp) ? W[(size_t)orow * Hp + k] : 0.f;
    }
    __syncthreads();
    for (int kk = 0; kk < 32; kk += 8) {
        int k = k0 + kk + threadIdx.y;
        if (k < Hp)
            Wt[(size_t)k * Gp + jblk * 32 + threadIdx.x] = tile[threadIdx.x][kk + threadIdx.y];
    }
}

// ---------------- bf16x2-split tensor-core GEMM (pre-split operands, ldmatrix) ----------------
__device__ __forceinline__ void mma_bf16(float4& d, const uint32_t* a, const uint32_t* b) {
    asm volatile(
        "mma.sync.aligned.m16n8k16.row.col.f32.bf16.bf16.f32 "
        "{%0,%1,%2,%3}, {%4,%5,%6,%7}, {%8,%9}, {%0,%1,%2,%3};\n"
        : "+f"(d.x), "+f"(d.y), "+f"(d.z), "+f"(d.w)
        : "r"(a[0]), "r"(a[1]), "r"(a[2]), "r"(a[3]), "r"(b[0]), "r"(b[1]));
}

__device__ __forceinline__ void ldm_x4(uint32_t* r, uint32_t saddr) {
    asm volatile("ldmatrix.sync.aligned.m8n8.x4.shared.b16 {%0,%1,%2,%3}, [%4];"
                 : "=r"(r[0]), "=r"(r[1]), "=r"(r[2]), "=r"(r[3]) : "r"(saddr));
}

__device__ __forceinline__ void ldm_x2(uint32_t* r, uint32_t saddr) {
    asm volatile("ldmatrix.sync.aligned.m8n8.x2.shared.b16 {%0,%1}, [%2];"
                 : "=r"(r[0]), "=r"(r[1]) : "r"(saddr));
}

#define WSTR 12   // b32 words per 16-k row (8 data + 4 pad)

// Ahg/Alg: [M][K/2] u32; Bhg/Blg: [N][K/2] u32. BM=BN=128, BK=16 floats (8 words).
// mode 0: C[m*N + n];  mode 1: C[((b*N + n)*T) + t], m = b*T + t (m-block = one b).
__global__ __launch_bounds__(256)
void gemm_tc(const uint32_t* __restrict__ Ahg, const uint32_t* __restrict__ Alg,
             const uint32_t* __restrict__ Bhg, const uint32_t* __restrict__ Blg,
             const float* __restrict__ bias1, const float* __restrict__ bias2,
             float* __restrict__ C, int M, int N, int K, int mode) {
    __shared__ uint32_t Ah[128 * WSTR];
    __shared__ uint32_t Al[128 * WSTR];
    __shared__ uint32_t Bh[128 * WSTR];
    __shared__ uint32_t Bl[128 * WSTR];

    const int tid  = threadIdx.x;
    const int lane = tid & 31;
    const int w    = tid >> 5;
    const int wm   = (w & 1) * 64;
    const int wn   = (w >> 1) * 32;
    const int qr   = lane >> 2;
    const int qc   = lane & 3;

    const int m0 = blockIdx.y * 128;
    const int n0 = blockIdx.x * 128;

    const int Kw = K >> 1;
    const int lrow = tid >> 1;
    const int lw   = (tid & 1) * 4;     // word offset within 8-word slab

    const uint32_t* Aph = Ahg + (size_t)(m0 + lrow) * Kw + lw;
    const uint32_t* Apl = Alg + (size_t)(m0 + lrow) * Kw + lw;
    const bool bvalid = (n0 + lrow) < N;
    const uint32_t* Bph = Bhg + (size_t)(bvalid ? (n0 + lrow) : 0) * Kw + lw;
    const uint32_t* Bpl = Blg + (size_t)(bvalid ? (n0 + lrow) : 0) * Kw + lw;
    const int sbase = lrow * WSTR + lw;

    const uint32_t uAh = (uint32_t)__cvta_generic_to_shared(Ah);
    const uint32_t uAl = (uint32_t)__cvta_generic_to_shared(Al);
    const uint32_t uBh = (uint32_t)__cvta_generic_to_shared(Bh);
    const uint32_t uBl = (uint32_t)__cvta_generic_to_shared(Bl);
    const uint32_t aoff = ((uint32_t)((wm + (lane & 15)) * WSTR + ((lane >> 4) << 2))) * 4u;
    const uint32_t boff = ((uint32_t)((wn + (lane & 7)) * WSTR + (((lane >> 3) & 1) << 2))) * 4u;

    float4 acc[4][4];
#pragma unroll
    for (int i = 0; i < 4; i++)
#pragma unroll
        for (int j = 0; j < 4; j++) acc[i][j] = make_float4(0.f, 0.f, 0.f, 0.f);

    const uint4 zero4 = make_uint4(0u, 0u, 0u, 0u);
    for (int kw = 0; kw < Kw; kw += 8) {
        uint4 ah4 = *(const uint4*)(Aph + kw);
        uint4 al4 = *(const uint4*)(Apl + kw);
        uint4 bh4 = bvalid ? *(const uint4*)(Bph + kw) : zero4;
        uint4 bl4 = bvalid ? *(const uint4*)(Bpl + kw) : zero4;
        __syncthreads();
        *(uint4*)&Ah[sbase] = ah4;
        *(uint4*)&Al[sbase] = al4;
        *(uint4*)&Bh[sbase] = bh4;
        *(uint4*)&Bl[sbase] = bl4;
        __syncthreads();

        uint32_t a_h[4][4], a_l[4][4];
#pragma unroll
        for (int mt = 0; mt < 4; mt++) {
            ldm_x4(a_h[mt], uAh + aoff + (uint32_t)(mt * 16 * WSTR * 4));
            ldm_x4(a_l[mt], uAl + aoff + (uint32_t)(mt * 16 * WSTR * 4));
        }
#pragma unroll
        for (int nt = 0; nt < 4; nt++) {
            uint32_t b_h[2], b_l[2];
            ldm_x2(b_h, uBh + boff + (uint32_t)(nt * 8 * WSTR * 4));
            ldm_x2(b_l, uBl + boff + (uint32_t)(nt * 8 * WSTR * 4));
#pragma unroll
            for (int mt = 0; mt < 4; mt++) {
                mma_bf16(acc[mt][nt], a_h[mt], b_h);
                mma_bf16(acc[mt][nt], a_h[mt], b_l);
                mma_bf16(acc[mt][nt], a_l[mt], b_h);
            }
        }
    }

#pragma unroll
    for (int mt = 0; mt < 4; mt++) {
        int mrow = m0 + wm + mt * 16 + qr;
#pragma unroll
        for (int nt = 0; nt < 4; nt++) {
            int n = n0 + wn + nt * 8 + 2 * qc;
            if (n >= N) continue;
            float b0 = 0.f, b1 = 0.f;
            if (bias1) { b0 += bias1[n]; b1 += bias1[n + 1]; }
            if (bias2) { b0 += bias2[n]; b1 += bias2[n + 1]; }
            float4 v = acc[mt][nt];
            if (mode == 0) {
                C[(size_t)mrow * N + n]           = v.x + b0;
                C[(size_t)mrow * N + n + 1]       = v.y + b1;
                C[(size_t)(mrow + 8) * N + n]     = v.z + b0;
                C[(size_t)(mrow + 8) * N + n + 1] = v.w + b1;
            } else {
                int bidx = m0 >> 7;
                int t = (mrow - m0);
                size_t base = ((size_t)bidx * N + n) * TSZ + t;
                C[base]           = v.x + b0;
                C[base + TSZ]     = v.y + b1;
                C[base + 8]       = v.z + b0;
                C[base + TSZ + 8] = v.w + b1;
            }
        }
    }
}

// ---------------- persistent LSTM layer kernel ----------------
__device__ __forceinline__ float sigf(float z) { return 1.f / (1.f + expf(-z)); }

#define FMA2(d, a, b) \
    asm("fma.rn.f32x2 %0, %1, %2, %0;" : "+l"(d) : "l"(a), "l"(b))

__device__ __forceinline__ void grid_bar_flags(unsigned* flags, int nCTA, unsigned target) {
    __syncthreads();
    if (threadIdx.x == 0) {
        asm volatile("st.release.gpu.global.u32 [%0], %1;"
                     :: "l"(flags + (size_t)blockIdx.x * FLAGSTRIDE), "r"(target) : "memory");
    }
    if (threadIdx.x < nCTA) {
        unsigned v;
        do {
            asm volatile("ld.acquire.gpu.global.u32 %0, [%1];"
                         : "=r"(v) : "l"(flags + (size_t)threadIdx.x * FLAGSTRIDE) : "memory");
        } while ((int)(v - target) < 0);
    }
    __syncthreads();
}

// Writes y as split bf16 word arrays Yh/Yl ([b*T+t][ldyw] u32), h state fp32,
// and final h/c into hOut/cOut.
__global__ __launch_bounds__(512, 1)
void lstm_layer_k(const float* __restrict__ pre, const float* __restrict__ Wt,
                  float* __restrict__ hA, float* __restrict__ hB,
                  float* __restrict__ cOut, float* __restrict__ hOut,
                  uint32_t* __restrict__ Yh, uint32_t* __restrict__ Yl,
                  int Hp, int Gp, int ldyw, unsigned* flags) {
    extern __shared__ float sm[];
    float* sW   = sm;
    float* red  = sm + Hp * 32;
    float* gsum = red + NSL * 32 * 16;
    float* cT   = gsum + 512;
    float* hrow = cT + 128;
    unsigned* sbase_p = (unsigned*)(hrow + 128);

    const int tid  = threadIdx.x;
    const int jblk = blockIdx.x;
    const int nCTA = gridDim.x;
    const int lane = tid & 31;
    const int s    = tid >> 5;
    const int bg   = lane >> 3;
    const int cg   = lane & 7;
    const int G4 = 4 * Hp;

    const int p_out = tid >> 2;
    const int p_g   = tid & 3;
    const int p_eb  = p_out & 15;
    const int p_eu  = p_out >> 4;
    const int p_ej  = jblk * 8 + p_eu;
    const bool p_act = p_ej < Hp;
    const int p_ebg = p_eb >> 2, p_ebi = p_eb & 3;
    const int p_co  = p_g * 8 + p_eu;
    const int p_cg2 = p_co >> 2, p_c2 = p_co & 3;

    const int eb = tid & 15;
    const int eu = tid >> 4;
    const int ej = jblk * 8 + eu;
    const bool eact = (tid < 128) && (ej < Hp);

    if (tid == 0) *sbase_p = flags[(size_t)jblk * FLAGSTRIDE];
    for (int idx = tid; idx < Hp * 32; idx += 512) {
        int k = idx >> 5, rr = idx & 31;
        sW[idx] = Wt[(size_t)k * Gp + jblk * 32 + rr];
    }
    if (tid < 128) {
        cT[tid] = 0.f;
        hrow[tid] = 0.f;
        if (ej < Hp) hA[ej * 16 + eb] = 0.f;
    }
    __syncthreads();
    const unsigned base = *sbase_p;

    float pg = 0.f;
    if (p_act)
        pg = __ldcg(pre + ((size_t)p_eb * TSZ + 0) * G4 + (size_t)p_g * Hp + p_ej);

    grid_bar_flags(flags, nCTA, base + 1u);

    const float4* sW4base = (const float4*)sW;

    for (int t = 0; t < TSZ; t++) {
        const float* hin = (t & 1) ? hB : hA;
        float* hout      = (t & 1) ? hA : hB;

        unsigned long long acc2[8];
#pragma unroll
        for (int i = 0; i < 8; i++) acc2[i] = 0ULL;

        const ulonglong2* hv = (const ulonglong2*)hin;
#pragma unroll 8
        for (int k = s; k < Hp; k += NSL) {
            float4 wq = sW4base[k * 8 + cg];
            ulonglong2 hp = hv[k * 4 + bg];
            unsigned long long w0, w1, w2, w3;
            asm("mov.b64 %0, {%1, %1};" : "=l"(w0) : "r"(__float_as_uint(wq.x)));
            asm("mov.b64 %0, {%1, %1};" : "=l"(w1) : "r"(__float_as_uint(wq.y)));
            asm("mov.b64 %0, {%1, %1};" : "=l"(w2) : "r"(__float_as_uint(wq.z)));
            asm("mov.b64 %0, {%1, %1};" : "=l"(w3) : "r"(__float_as_uint(wq.w)));
            FMA2(acc2[0], w0, hp.x); FMA2(acc2[1], w0, hp.y);
            FMA2(acc2[2], w1, hp.x); FMA2(acc2[3], w1, hp.y);
            FMA2(acc2[4], w2, hp.x); FMA2(acc2[5], w2, hp.y);
            FMA2(acc2[6], w3, hp.x); FMA2(acc2[7], w3, hp.y);
        }

        ulonglong2* rp = (ulonglong2*)&red[(s * 32 + lane) * 16];
        rp[0] = make_ulonglong2(acc2[0], acc2[1]);
        rp[1] = make_ulonglong2(acc2[2], acc2[3]);
        rp[2] = make_ulonglong2(acc2[4], acc2[5]);
        rp[3] = make_ulonglong2(acc2[6], acc2[7]);
        __syncthreads();

        {
            float sum = pg;
            int ridx = (p_ebg * 8 + p_cg2) * 16 + p_c2 * 4 + p_ebi;
#pragma unroll
            for (int s2 = 0; s2 < NSL; s2++)
                sum += red[s2 * 512 + ridx];
            gsum[tid] = sum;
        }
        __syncthreads();

        if (eact) {
            float4 gv = *(const float4*)&gsum[tid * 4];
            float ig = sigf(gv.x);
            float fg = sigf(gv.y);
            float gg = tanhf(gv.z);
            float og = sigf(gv.w);
            float c  = fg * cT[tid] + ig * gg;
            float hn = og * tanhf(c);
            cT[tid] = c;
            hrow[tid] = hn;
            __stcg(&hout[ej * 16 + eb], hn);
            if (t == TSZ - 1) {
                cOut[ej * 16 + eb] = c;
                hOut[ej * 16 + eb] = hn;
            }
        }
        __syncthreads();

        // pack 2 columns -> one split word; 64 threads write Yh/Yl
        if (tid < 64) {
            int q = tid >> 4, b = tid & 15;
            float v0 = hrow[(2 * q) * 16 + b];
            float v1 = hrow[(2 * q + 1) * 16 + b];
            uint32_t h, l;
            bfsplit2(v0, v1, h, l);
            size_t wrow = (size_t)b * TSZ + t;
            Yh[wrow * ldyw + jblk * 4 + q] = h;
            Yl[wrow * ldyw + jblk * 4 + q] = l;
        }

        float pgn = 0.f;
        if (p_act && t + 1 < TSZ)
            pgn = __ldcg(pre + ((size_t)p_eb * TSZ + t + 1) * G4 + (size_t)p_g * Hp + p_ej);

        grid_bar_flags(flags, nCTA, base + (unsigned)(t + 2));
        pg = pgn;
    }
}

// ---------------- finalize ----------------
__global__ void finalize_k(const float* __restrict__ hO1, const float* __restrict__ hO2,
                           const float* __restrict__ hO3, const float* __restrict__ cT1,
                           const float* __restrict__ cT2, const float* __restrict__ cT3,
                           float* __restrict__ out) {
    int i = blockIdx.x * blockDim.x + threadIdx.x;
    if (i >= 86400) return;
    const size_t O = (size_t)BSZ * VSZ * TSZ;
    if (i < 18400) {
        int b = i / 1150, j = i % 1150;
        out[O + i] = hO1[j * 16 + b];
    } else if (i < 36800) {
        int k = i - 18400; int b = k / 1150, j = k % 1150;
        out[O + i] = hO2[j * 16 + b];
    } else if (i < 43200) {
        int k = i - 36800; int b = k / 400, j = k % 400;
        out[O + i] = hO3[j * 16 + b];
    } else if (i < 61600) {
        int k = i - 43200; int j = (k % 1150), b = k / 1150;
        out[O + i] = cT1[j * 16 + b];
    } else if (i < 80000) {
        int k = i - 61600; int j = (k % 1150), b = k / 1150;
        out[O + i] = cT2[j * 16 + b];
    } else {
        int k = i - 80000; int j = (k % 400), b = k / 400;
        out[O + i] = cT3[j * 16 + b];
    }
}

// ---------------- launch ----------------
extern "C" void kernel_launch(void* const* d_in, const int* in_sizes, int n_in,
                              void* d_out, int out_size) {
    const float* emb  = (const float*)d_in[0];
    const float* Wih1 = (const float*)d_in[1];
    const float* Whh1 = (const float*)d_in[2];
    const float* bih1 = (const float*)d_in[3];
    const float* bhh1 = (const float*)d_in[4];
    const float* Wih2 = (const float*)d_in[5];
    const float* Whh2 = (const float*)d_in[6];
    const float* bih2 = (const float*)d_in[7];
    const float* bhh2 = (const float*)d_in[8];
    const float* Wih3 = (const float*)d_in[9];
    const float* Whh3 = (const float*)d_in[10];
    const float* bih3 = (const float*)d_in[11];
    const float* bhh3 = (const float*)d_in[12];
    const float* linb = (const float*)d_in[13];
    const int*   x    = (const int*)d_in[14];
    float* out = (float*)d_out;

    uint32_t *y0h, *y0l, *y1h, *y1l, *y2h, *y2l, *y3h, *y3l;
    uint32_t *W1h, *W1l, *W2h, *W2l, *W3h, *W3l, *Eh, *El;
    float *pre, *Wt1, *Wt2, *Wt3, *hTa, *hTb, *cT1, *cT2, *cT3, *hO1, *hO2, *hO3;
    unsigned* flags;
    cudaGetSymbolAddress((void**)&y0h, g_y0h); cudaGetSymbolAddress((void**)&y0l, g_y0l);
    cudaGetSymbolAddress((void**)&y1h, g_y1h); cudaGetSymbolAddress((void**)&y1l, g_y1l);
    cudaGetSymbolAddress((void**)&y2h, g_y2h); cudaGetSymbolAddress((void**)&y2l, g_y2l);
    cudaGetSymbolAddress((void**)&y3h, g_y3h); cudaGetSymbolAddress((void**)&y3l, g_y3l);
    cudaGetSymbolAddress((void**)&W1h, g_W1h); cudaGetSymbolAddress((void**)&W1l, g_W1l);
    cudaGetSymbolAddress((void**)&W2h, g_W2h); cudaGetSymbolAddress((void**)&W2l, g_W2l);
    cudaGetSymbolAddress((void**)&W3h, g_W3h); cudaGetSymbolAddress((void**)&W3l, g_W3l);
    cudaGetSymbolAddress((void**)&Eh,  g_Eh);  cudaGetSymbolAddress((void**)&El,  g_El);
    cudaGetSymbolAddress((void**)&pre, g_pre);
    cudaGetSymbolAddress((void**)&Wt1, g_Wt1);
    cudaGetSymbolAddress((void**)&Wt2, g_Wt2);
    cudaGetSymbolAddress((void**)&Wt3, g_Wt3);
    cudaGetSymbolAddress((void**)&hTa, g_hTa);
    cudaGetSymbolAddress((void**)&hTb, g_hTb);
    cudaGetSymbolAddress((void**)&cT1, g_cT1);
    cudaGetSymbolAddress((void**)&cT2, g_cT2);
    cudaGetSymbolAddress((void**)&cT3, g_cT3);
    cudaGetSymbolAddress((void**)&hO1, g_hO1);
    cudaGetSymbolAddress((void**)&hO2, g_hO2);
    cudaGetSymbolAddress((void**)&hO3, g_hO3);
    cudaGetSymbolAddress((void**)&flags, g_flags);

    const int M = TSZ * BSZ;  // 2048
    const int SMEM12 = (HSZ * 32 + NSL * 32 * 16 + 512 + 128 + 128 + 32) * 4;
    const int SMEM3  = (ESZ * 32 + NSL * 32 * 16 + 512 + 128 + 128 + 32) * 4;
    static int smem_set = 0;
    if (!smem_set) {
        cudaFuncSetAttribute(lstm_layer_k, cudaFuncAttributeMaxDynamicSharedMemorySize, SMEM12);
        smem_set = 1;
    }

    // ----- layer 1: embed2 -> wtrans1 -> splitW1 -> gemm1 (4th: profiled) -----
    embed2_k<<<(M * 200 + 255) / 256, 256>>>(emb, x, y0h, y0l);
    wtrans_k<<<dim3(GP12 / 32, (HSZ + 31) / 32), dim3(32, 8)>>>(Whh1, Wt1, HSZ, GP12);
    split2_k<<<(4 * HSZ * 200 + 255) / 256, 256>>>(Wih1, W1h, W1l, 4 * HSZ * 200);
    gemm_tc<<<dim3((4 * HSZ + 127) / 128, M / 128), 256>>>(
        y0h, y0l, W1h, W1l, bih1, bhh1, pre, M, 4 * HSZ, ESZ, 0);
    lstm_layer_k<<<GP12 / 32, 512, SMEM12>>>(pre, Wt1, hTa, hTb, cT1, hO1, y1h, y1l,
                                             HSZ, GP12, 576, flags + 0 * 144 * FLAGSTRIDE);

    // ----- layer 2 -----
    padsplit2_k<<<(4 * HSZ * 576 + 255) / 256, 256>>>(Wih2, W2h, W2l, 4 * HSZ, HSZ, 576);
    wtrans_k<<<dim3(GP12 / 32, (HSZ + 31) / 32), dim3(32, 8)>>>(Whh2, Wt2, HSZ, GP12);
    gemm_tc<<<dim3((4 * HSZ + 127) / 128, M / 128), 256>>>(
        y1h, y1l, W2h, W2l, bih2, bhh2, pre, M, 4 * HSZ, HPAD, 0);
    lstm_layer_k<<<GP12 / 32, 512, SMEM12>>>(pre, Wt2, hTa, hTb, cT2, hO2, y2h, y2l,
                                             HSZ, GP12, 576, flags + 1 * 144 * FLAGSTRIDE);

    // ----- layer 3 -----
    padsplit2_k<<<(4 * ESZ * 576 + 255) / 256, 256>>>(Wih3, W3h, W3l, 4 * ESZ, HSZ, 576);
    wtrans_k<<<dim3(GP3 / 32, (ESZ + 31) / 32), dim3(32, 8)>>>(Whh3, Wt3, ESZ, GP3);
    gemm_tc<<<dim3((4 * ESZ + 127) / 128, M / 128), 256>>>(
        y2h, y2l, W3h, W3l, bih3, bhh3, pre, M, 4 * ESZ, HPAD, 0);
    lstm_layer_k<<<GP3 / 32, 512, SMEM3>>>(pre, Wt3, hTa, hTb, cT3, hO3, y3h, y3l,
                                           ESZ, GP3, 200, flags + 2 * 144 * FLAGSTRIDE);

    // ----- tied output projection into (B,V,T) -----
    split2_k<<<(VSZ * 200 + 255) / 256, 256>>>(emb, Eh, El, VSZ * 200);
    gemm_tc<<<dim3(VSZ / 128, M / 128), 256>>>(
        y3h, y3l, Eh, El, linb, nullptr, out, M, VSZ, ESZ, 1);

    // ----- final states -----
    finalize_k<<<(86400 + 255) / 256, 256>>>(hO1, hO2, hO3, cT1, cT2, cT3, out);
}